// round 1
// baseline (speedup 1.0000x reference)
#include <cuda_runtime.h>
#include <cuda_bf16.h>
#include <cstdint>

// ---------------- problem constants ----------------
constexpr int HDIM = 2048;   // hidden
constexpr int IDIM = 1408;   // intermediate
constexpr int NEXP = 16;     // experts
constexpr int TMAX = 8192;   // max tokens
constexpr int RMAX = 2 * TMAX;

// ---------------- device scratch (static, no allocs) ----------------
__device__ int   g_counts[NEXP];
__device__ int   g_cursors[NEXP];
__device__ int   g_offs[NEXP + 1];
__device__ int   g_topk_i[RMAX];
__device__ float g_topk_w[RMAX];
__device__ int   g_rows_t[RMAX];
__device__ float g_rows_w[RMAX];
__device__ float g_hbuf[(size_t)RMAX * IDIM];   // GEMM1 output (silu(g)*u), fp32

// ---------------- asm helpers ----------------
#define LDSM4(R, addr)                                                        \
  asm volatile("ldmatrix.sync.aligned.m8n8.x4.shared.b16 {%0,%1,%2,%3},[%4];" \
               : "=r"((R)[0]), "=r"((R)[1]), "=r"((R)[2]), "=r"((R)[3])       \
               : "r"(addr))

#define LDSM4T(R, addr)                                                             \
  asm volatile("ldmatrix.sync.aligned.m8n8.x4.trans.shared.b16 {%0,%1,%2,%3},[%4];" \
               : "=r"((R)[0]), "=r"((R)[1]), "=r"((R)[2]), "=r"((R)[3])             \
               : "r"(addr))

#define MMA16816(D, A, B)                                                     \
  asm volatile("mma.sync.aligned.m16n8k16.row.col.f32.bf16.bf16.f32 "         \
               "{%0,%1,%2,%3},{%4,%5,%6,%7},{%8,%9},{%0,%1,%2,%3};"           \
               : "+f"((D)[0]), "+f"((D)[1]), "+f"((D)[2]), "+f"((D)[3])       \
               : "r"((A)[0]), "r"((A)[1]), "r"((A)[2]), "r"((A)[3]),          \
                 "r"((B)[0]), "r"((B)[1]))

__device__ __forceinline__ __nv_bfloat162 split_hi(float a, float b) {
  return __floats2bfloat162_rn(a, b);
}
__device__ __forceinline__ __nv_bfloat162 split_lo(float a, float b, __nv_bfloat162 h) {
  return __floats2bfloat162_rn(a - __bfloat162float(__low2bfloat16(h)),
                               b - __bfloat162float(__high2bfloat16(h)));
}

// ---------------- router: logits -> top2 -> renorm ----------------
__global__ void router_kernel(const float* __restrict__ x,
                              const float* __restrict__ gw, int T) {
  int gwarp = (blockIdx.x * blockDim.x + threadIdx.x) >> 5;
  int lane = threadIdx.x & 31;
  if (gwarp >= T) return;
  const float* xr = x + (size_t)gwarp * HDIM;
  float acc[NEXP];
#pragma unroll
  for (int j = 0; j < NEXP; j++) acc[j] = 0.f;
  for (int k = lane; k < HDIM; k += 32) {
    float xv = xr[k];
    const float4* g4 = (const float4*)(gw + (size_t)k * NEXP);
#pragma unroll
    for (int q = 0; q < 4; q++) {
      float4 g = g4[q];
      acc[q * 4 + 0] += xv * g.x;
      acc[q * 4 + 1] += xv * g.y;
      acc[q * 4 + 2] += xv * g.z;
      acc[q * 4 + 3] += xv * g.w;
    }
  }
#pragma unroll
  for (int j = 0; j < NEXP; j++) {
#pragma unroll
    for (int o = 16; o > 0; o >>= 1)
      acc[j] += __shfl_xor_sync(0xffffffffu, acc[j], o);
  }
  if (lane == 0) {
    float b = -3.4e38f, s = -3.4e38f;
    int bi = 0, si = 0;
#pragma unroll
    for (int j = 0; j < NEXP; j++) {
      float v = acc[j];
      if (v > b) { s = b; si = bi; b = v; bi = j; }
      else if (v > s) { s = v; si = j; }
    }
    // softmax + top2 renorm == 1/(1+exp(l2-l1))
    float w0 = 1.f / (1.f + expf(s - b));
    g_topk_i[gwarp * 2 + 0] = bi;
    g_topk_i[gwarp * 2 + 1] = si;
    g_topk_w[gwarp * 2 + 0] = w0;
    g_topk_w[gwarp * 2 + 1] = 1.f - w0;
  }
}

// ---------------- routing bookkeeping ----------------
__global__ void zero_cnt_kernel() {
  if (threadIdx.x < NEXP) g_counts[threadIdx.x] = 0;
}
__global__ void hist_kernel(int R) {
  int i = blockIdx.x * blockDim.x + threadIdx.x;
  if (i < R) atomicAdd(&g_counts[g_topk_i[i]], 1);
}
__global__ void scan_kernel() {
  int s = 0;
  for (int e = 0; e < NEXP; e++) {
    g_offs[e] = s;
    g_cursors[e] = s;
    s += g_counts[e];
  }
  g_offs[NEXP] = s;
}
__global__ void scatter_kernel(int R) {
  int i = blockIdx.x * blockDim.x + threadIdx.x;
  if (i >= R) return;
  int e = g_topk_i[i];
  int pos = atomicAdd(&g_cursors[e], 1);
  g_rows_t[pos] = i >> 1;
  g_rows_w[pos] = g_topk_w[i];
}

// ---------------- GEMM1: h = silu(Xe@w1) * (Xe@w3) ----------------
// BM=128, BN=64 (per matrix), BK=32, 256 threads, warp grid 4(M)x2(N), warp tile 32x32 per matrix
__global__ __launch_bounds__(256, 1) void gemm1_kernel(
    const float* __restrict__ x, const float* __restrict__ w1,
    const float* __restrict__ w3) {
  const int e = blockIdx.z;
  const int base = g_offs[e];
  const int cnt = g_offs[e + 1] - base;
  const int m0 = blockIdx.x * 128;
  if (m0 >= cnt) return;
  const int n0 = blockIdx.y * 64;

  __shared__ __nv_bfloat16 As[2][128 * 40];       // [hi/lo][row*40+k]
  __shared__ __nv_bfloat16 Bs[2][2][32 * 72];     // [hi/lo][w1/w3][k*72+n]

  const int tid = threadIdx.x;
  const int lane = tid & 31;
  const int warp = tid >> 5;
  const int wm = warp >> 1;  // 0..3
  const int wn = warp & 1;   // 0..1

  // A staging: thread -> (row = tid/2, k-half = (tid&1)*16), 4 float4
  const int ar = tid >> 1;
  const int ak = (tid & 1) * 16;
  int arow = m0 + ar;
  const int tokA = g_rows_t[base + (arow < cnt ? arow : 0)];
  const float* aptr = x + (size_t)tokA * HDIM + ak;

  // B staging: thread -> row=tid/8, 2 float4 per matrix
  const int bkr = tid >> 3;
  const int bc0 = (tid & 7) * 8;  // float col of first float4
  const size_t wbase = (size_t)e * HDIM * IDIM + (size_t)bkr * IDIM + n0 + bc0;
  const float* b1p = w1 + wbase;
  const float* b3p = w3 + wbase;

  float4 aS[4], b1S[2], b3S[2];

  float accg[2][4][4], accu[2][4][4];
#pragma unroll
  for (int i = 0; i < 2; i++)
#pragma unroll
    for (int j = 0; j < 4; j++)
#pragma unroll
      for (int k = 0; k < 4; k++) { accg[i][j][k] = 0.f; accu[i][j][k] = 0.f; }

  const uint32_t as_hi = (uint32_t)__cvta_generic_to_shared(&As[0][0]);
  const uint32_t as_lo = (uint32_t)__cvta_generic_to_shared(&As[1][0]);
  const uint32_t b1hA = (uint32_t)__cvta_generic_to_shared(&Bs[0][0][0]);
  const uint32_t b1lA = (uint32_t)__cvta_generic_to_shared(&Bs[1][0][0]);
  const uint32_t b3hA = (uint32_t)__cvta_generic_to_shared(&Bs[0][1][0]);
  const uint32_t b3lA = (uint32_t)__cvta_generic_to_shared(&Bs[1][1][0]);

  const int a_r = wm * 32 + (lane & 15);
  const int a_k = (lane >> 4) * 8;
  const int b_r = lane & 15;
  const int b_c = wn * 32 + (lane >> 4) * 8;

  const int KT = HDIM / 32;

  // prologue
#pragma unroll
  for (int j = 0; j < 4; j++) aS[j] = *(const float4*)(aptr + j * 4);
#pragma unroll
  for (int q = 0; q < 2; q++) {
    b1S[q] = *(const float4*)(b1p + q * 4);
    b3S[q] = *(const float4*)(b3p + q * 4);
  }

  for (int kt = 0; kt < KT; kt++) {
    __syncthreads();
    // ---- convert + store stage ----
#pragma unroll
    for (int j = 0; j < 4; j++) {
      float4 f = aS[j];
      int col = ak + j * 4;
      __nv_bfloat162 h01 = split_hi(f.x, f.y), h23 = split_hi(f.z, f.w);
      __nv_bfloat162 l01 = split_lo(f.x, f.y, h01), l23 = split_lo(f.z, f.w, h23);
      *(__nv_bfloat162*)&As[0][ar * 40 + col] = h01;
      *(__nv_bfloat162*)&As[0][ar * 40 + col + 2] = h23;
      *(__nv_bfloat162*)&As[1][ar * 40 + col] = l01;
      *(__nv_bfloat162*)&As[1][ar * 40 + col + 2] = l23;
    }
#pragma unroll
    for (int q = 0; q < 2; q++) {
      int idx = bkr * 72 + bc0 + q * 4;
      {
        float4 f = b1S[q];
        __nv_bfloat162 h01 = split_hi(f.x, f.y), h23 = split_hi(f.z, f.w);
        __nv_bfloat162 l01 = split_lo(f.x, f.y, h01), l23 = split_lo(f.z, f.w, h23);
        *(__nv_bfloat162*)&Bs[0][0][idx] = h01;
        *(__nv_bfloat162*)&Bs[0][0][idx + 2] = h23;
        *(__nv_bfloat162*)&Bs[1][0][idx] = l01;
        *(__nv_bfloat162*)&Bs[1][0][idx + 2] = l23;
      }
      {
        float4 f = b3S[q];
        __nv_bfloat162 h01 = split_hi(f.x, f.y), h23 = split_hi(f.z, f.w);
        __nv_bfloat162 l01 = split_lo(f.x, f.y, h01), l23 = split_lo(f.z, f.w, h23);
        *(__nv_bfloat162*)&Bs[0][1][idx] = h01;
        *(__nv_bfloat162*)&Bs[0][1][idx + 2] = h23;
        *(__nv_bfloat162*)&Bs[1][1][idx] = l01;
        *(__nv_bfloat162*)&Bs[1][1][idx + 2] = l23;
      }
    }
    __syncthreads();
    // ---- prefetch next stage into registers ----
    if (kt + 1 < KT) {
      const float* ap = aptr + (kt + 1) * 32;
#pragma unroll
      for (int j = 0; j < 4; j++) aS[j] = *(const float4*)(ap + j * 4);
      const size_t koff = (size_t)(kt + 1) * 32 * IDIM;
#pragma unroll
      for (int q = 0; q < 2; q++) {
        b1S[q] = *(const float4*)(b1p + koff + q * 4);
        b3S[q] = *(const float4*)(b3p + koff + q * 4);
      }
    }
    // ---- MMAs ----
#pragma unroll
    for (int ks = 0; ks < 2; ks++) {
      uint32_t a_h[2][4], a_l[2][4];
#pragma unroll
      for (int mt = 0; mt < 2; mt++) {
        uint32_t off = (uint32_t)(((a_r + mt * 16) * 40 + ks * 16 + a_k) << 1);
        LDSM4(a_h[mt], as_hi + off);
        LDSM4(a_l[mt], as_lo + off);
      }
      uint32_t b1h[2][4], b1l[2][4], b3h[2][4], b3l[2][4];
#pragma unroll
      for (int hlf = 0; hlf < 2; hlf++) {
        uint32_t off = (uint32_t)((((ks * 16 + b_r) * 72) + b_c + hlf * 16) << 1);
        LDSM4T(b1h[hlf], b1hA + off);
        LDSM4T(b1l[hlf], b1lA + off);
        LDSM4T(b3h[hlf], b3hA + off);
        LDSM4T(b3l[hlf], b3lA + off);
      }
#pragma unroll
      for (int mt = 0; mt < 2; mt++) {
#pragma unroll
        for (int nt = 0; nt < 4; nt++) {
          const uint32_t* bg1h = &b1h[nt >> 1][(nt & 1) * 2];
          const uint32_t* bg1l = &b1l[nt >> 1][(nt & 1) * 2];
          const uint32_t* bg3h = &b3h[nt >> 1][(nt & 1) * 2];
          const uint32_t* bg3l = &b3l[nt >> 1][(nt & 1) * 2];
          MMA16816(accg[mt][nt], a_h[mt], bg1h);   // hi*hi
          MMA16816(accg[mt][nt], a_h[mt], bg1l);   // hi*lo
          MMA16816(accg[mt][nt], a_l[mt], bg1h);   // lo*hi
          MMA16816(accu[mt][nt], a_h[mt], bg3h);
          MMA16816(accu[mt][nt], a_h[mt], bg3l);
          MMA16816(accu[mt][nt], a_l[mt], bg3h);
        }
      }
    }
  }

  // ---- epilogue: silu(g)*u -> hbuf ----
#pragma unroll
  for (int mt = 0; mt < 2; mt++) {
    int rb = wm * 32 + mt * 16 + (lane >> 2);
#pragma unroll
    for (int hlf = 0; hlf < 2; hlf++) {
      int r = rb + hlf * 8;
      if (m0 + r >= cnt) continue;
      float* hrow = g_hbuf + (size_t)(base + m0 + r) * IDIM + n0 + wn * 32;
#pragma unroll
      for (int nt = 0; nt < 4; nt++) {
        float gg0 = accg[mt][nt][hlf * 2 + 0], gg1 = accg[mt][nt][hlf * 2 + 1];
        float uu0 = accu[mt][nt][hlf * 2 + 0], uu1 = accu[mt][nt][hlf * 2 + 1];
        float h0 = gg0 / (1.f + __expf(-gg0)) * uu0;
        float h1 = gg1 / (1.f + __expf(-gg1)) * uu1;
        int col = nt * 8 + (lane & 3) * 2;
        hrow[col] = h0;
        hrow[col + 1] = h1;
      }
    }
  }
}

// ---------------- GEMM2: out[t] += w * (h @ w2_e) ----------------
// BM=128, BN=128, BK=32, 256 threads, warp grid 4(M)x2(N), warp tile 32x64
__global__ __launch_bounds__(256, 1) void gemm2_kernel(
    const float* __restrict__ w2, float* __restrict__ out) {
  const int e = blockIdx.z;
  const int base = g_offs[e];
  const int cnt = g_offs[e + 1] - base;
  const int m0 = blockIdx.x * 128;
  if (m0 >= cnt) return;
  const int n0 = blockIdx.y * 128;

  __shared__ __nv_bfloat16 As[2][128 * 40];
  __shared__ __nv_bfloat16 Bs[2][32 * 136];

  const int tid = threadIdx.x;
  const int lane = tid & 31;
  const int warp = tid >> 5;
  const int wm = warp >> 1;
  const int wn = warp & 1;

  const int ar = tid >> 1;
  const int ak = (tid & 1) * 16;
  int arow = m0 + ar;
  const float* aptr = g_hbuf + (size_t)(base + (arow < cnt ? arow : 0)) * IDIM + ak;

  const int bkr = tid >> 3;   // 0..31 (k-row)
  const int bc = tid & 7;     // float4 group
  const float* bp = w2 + (size_t)e * IDIM * HDIM + (size_t)bkr * HDIM + n0;

  float4 aS[4], bS[4];

  float acc[2][8][4];
#pragma unroll
  for (int i = 0; i < 2; i++)
#pragma unroll
    for (int j = 0; j < 8; j++)
#pragma unroll
      for (int k = 0; k < 4; k++) acc[i][j][k] = 0.f;

  const uint32_t as_hi = (uint32_t)__cvta_generic_to_shared(&As[0][0]);
  const uint32_t as_lo = (uint32_t)__cvta_generic_to_shared(&As[1][0]);
  const uint32_t bs_hi = (uint32_t)__cvta_generic_to_shared(&Bs[0][0]);
  const uint32_t bs_lo = (uint32_t)__cvta_generic_to_shared(&Bs[1][0]);

  const int a_r = wm * 32 + (lane & 15);
  const int a_k = (lane >> 4) * 8;
  const int b_r = lane & 15;
  const int b_c0 = wn * 64 + (lane >> 4) * 8;

  const int KT = IDIM / 32;  // 44

  // prologue
#pragma unroll
  for (int j = 0; j < 4; j++) aS[j] = *(const float4*)(aptr + j * 4);
#pragma unroll
  for (int j = 0; j < 4; j++) bS[j] = *(const float4*)(bp + (bc + 8 * j) * 4);

  for (int kt = 0; kt < KT; kt++) {
    __syncthreads();
#pragma unroll
    for (int j = 0; j < 4; j++) {
      float4 f = aS[j];
      int col = ak + j * 4;
      __nv_bfloat162 h01 = split_hi(f.x, f.y), h23 = split_hi(f.z, f.w);
      __nv_bfloat162 l01 = split_lo(f.x, f.y, h01), l23 = split_lo(f.z, f.w, h23);
      *(__nv_bfloat162*)&As[0][ar * 40 + col] = h01;
      *(__nv_bfloat162*)&As[0][ar * 40 + col + 2] = h23;
      *(__nv_bfloat162*)&As[1][ar * 40 + col] = l01;
      *(__nv_bfloat162*)&As[1][ar * 40 + col + 2] = l23;
    }
#pragma unroll
    for (int j = 0; j < 4; j++) {
      float4 f = bS[j];
      int idx = bkr * 136 + (bc + 8 * j) * 4;
      __nv_bfloat162 h01 = split_hi(f.x, f.y), h23 = split_hi(f.z, f.w);
      __nv_bfloat162 l01 = split_lo(f.x, f.y, h01), l23 = split_lo(f.z, f.w, h23);
      *(__nv_bfloat162*)&Bs[0][idx] = h01;
      *(__nv_bfloat162*)&Bs[0][idx + 2] = h23;
      *(__nv_bfloat162*)&Bs[1][idx] = l01;
      *(__nv_bfloat162*)&Bs[1][idx + 2] = l23;
    }
    __syncthreads();
    if (kt + 1 < KT) {
      const float* ap = aptr + (kt + 1) * 32;
#pragma unroll
      for (int j = 0; j < 4; j++) aS[j] = *(const float4*)(ap + j * 4);
      const float* bpp = bp + (size_t)(kt + 1) * 32 * HDIM;
#pragma unroll
      for (int j = 0; j < 4; j++) bS[j] = *(const float4*)(bpp + (bc + 8 * j) * 4);
    }
#pragma unroll
    for (int ks = 0; ks < 2; ks++) {
      uint32_t a_h[2][4], a_l[2][4];
#pragma unroll
      for (int mt = 0; mt < 2; mt++) {
        uint32_t off = (uint32_t)(((a_r + mt * 16) * 40 + ks * 16 + a_k) << 1);
        LDSM4(a_h[mt], as_hi + off);
        LDSM4(a_l[mt], as_lo + off);
      }
      uint32_t bh[4][4], bl[4][4];
#pragma unroll
      for (int hlf = 0; hlf < 4; hlf++) {
        uint32_t off = (uint32_t)((((ks * 16 + b_r) * 136) + b_c0 + hlf * 16) << 1);
        LDSM4T(bh[hlf], bs_hi + off);
        LDSM4T(bl[hlf], bs_lo + off);
      }
#pragma unroll
      for (int mt = 0; mt < 2; mt++) {
#pragma unroll
        for (int nt = 0; nt < 8; nt++) {
          const uint32_t* pbh = &bh[nt >> 1][(nt & 1) * 2];
          const uint32_t* pbl = &bl[nt >> 1][(nt & 1) * 2];
          MMA16816(acc[mt][nt], a_h[mt], pbh);
          MMA16816(acc[mt][nt], a_h[mt], pbl);
          MMA16816(acc[mt][nt], a_l[mt], pbh);
        }
      }
    }
  }

  // epilogue: weighted atomic scatter-add
#pragma unroll
  for (int mt = 0; mt < 2; mt++) {
    int rb = wm * 32 + mt * 16 + (lane >> 2);
#pragma unroll
    for (int hlf = 0; hlf < 2; hlf++) {
      int r = rb + hlf * 8;
      int gr = m0 + r;
      if (gr >= cnt) continue;
      int tok = g_rows_t[base + gr];
      float w = g_rows_w[base + gr];
      float* orow = out + (size_t)tok * HDIM + n0 + wn * 64;
#pragma unroll
      for (int nt = 0; nt < 8; nt++) {
        int col = nt * 8 + (lane & 3) * 2;
        atomicAdd(&orow[col], acc[mt][nt][hlf * 2 + 0] * w);
        atomicAdd(&orow[col + 1], acc[mt][nt][hlf * 2 + 1] * w);
      }
    }
  }
}

// ---------------- launch ----------------
extern "C" void kernel_launch(void* const* d_in, const int* in_sizes, int n_in,
                              void* d_out, int out_size) {
  const float* x  = (const float*)d_in[0];
  const float* gw = (const float*)d_in[1];
  const float* w1 = (const float*)d_in[2];
  const float* w3 = (const float*)d_in[3];
  const float* w2 = (const float*)d_in[4];
  float* out = (float*)d_out;

  const int T = in_sizes[0] / HDIM;   // 8192
  const int R = 2 * T;

  cudaMemsetAsync(out, 0, (size_t)out_size * sizeof(float), 0);

  zero_cnt_kernel<<<1, 32>>>();
  router_kernel<<<(T + 7) / 8, 256>>>(x, gw, T);
  hist_kernel<<<(R + 255) / 256, 256>>>(R);
  scan_kernel<<<1, 1>>>();
  scatter_kernel<<<(R + 255) / 256, 256>>>(R);

  const int mtiles = (T + 127) / 128;  // worst case: one expert takes all tokens
  dim3 g1(mtiles, IDIM / 64, NEXP);
  gemm1_kernel<<<g1, 256>>>(x, w1, w3);
  dim3 g2(mtiles, HDIM / 128, NEXP);
  gemm2_kernel<<<g2, 256>>>(w2, out);
}

// round 2
// speedup vs baseline: 1.5313x; 1.5313x over previous
#include <cuda_runtime.h>
#include <cuda_fp16.h>
#include <cstdint>

// ---------------- problem constants ----------------
constexpr int HDIM = 2048;
constexpr int IDIM = 1408;
constexpr int NEXP = 16;
constexpr int TMAX = 8192;
constexpr int RMAX = 2 * TMAX;

// ---------------- device scratch (static, no runtime allocs) ----------------
__device__ int   g_counts[NEXP];
__device__ int   g_cursors[NEXP];
__device__ int   g_offs[NEXP + 1];
__device__ int   g_topk_i[RMAX];
__device__ float g_topk_w[RMAX];
__device__ int   g_rows_t[RMAX];
__device__ float g_rows_w[RMAX];

__device__ alignas(16) __half g_w1h[(size_t)NEXP * HDIM * IDIM];
__device__ alignas(16) __half g_w3h[(size_t)NEXP * HDIM * IDIM];
__device__ alignas(16) __half g_w2h[(size_t)NEXP * IDIM * HDIM];
__device__ alignas(16) __half g_xh[(size_t)TMAX * HDIM];
__device__ alignas(16) __half g_xl[(size_t)TMAX * HDIM];
__device__ alignas(16) __half g_hh[(size_t)RMAX * IDIM];
__device__ alignas(16) __half g_hl[(size_t)RMAX * IDIM];

// ---------------- asm helpers ----------------
#define LDSM4(R, addr)                                                        \
  asm volatile("ldmatrix.sync.aligned.m8n8.x4.shared.b16 {%0,%1,%2,%3},[%4];" \
               : "=r"((R)[0]), "=r"((R)[1]), "=r"((R)[2]), "=r"((R)[3])       \
               : "r"(addr))

#define LDSM4T(R, addr)                                                             \
  asm volatile("ldmatrix.sync.aligned.m8n8.x4.trans.shared.b16 {%0,%1,%2,%3},[%4];" \
               : "=r"((R)[0]), "=r"((R)[1]), "=r"((R)[2]), "=r"((R)[3])             \
               : "r"(addr))

#define MMAF16(D, A, B)                                                       \
  asm volatile("mma.sync.aligned.m16n8k16.row.col.f32.f16.f16.f32 "           \
               "{%0,%1,%2,%3},{%4,%5,%6,%7},{%8,%9},{%0,%1,%2,%3};"           \
               : "+f"((D)[0]), "+f"((D)[1]), "+f"((D)[2]), "+f"((D)[3])       \
               : "r"((A)[0]), "r"((A)[1]), "r"((A)[2]), "r"((A)[3]),          \
                 "r"((B)[0]), "r"((B)[1]))

#define CP16(dst, src)                                                        \
  asm volatile("cp.async.cg.shared.global [%0],[%1],16;" ::"r"(dst), "l"(src))
#define CPCOMMIT() asm volatile("cp.async.commit_group;")
#define CPWAIT1() asm volatile("cp.async.wait_group 1;")

// ---------------- conversion pre-pass ----------------
__global__ void convw_kernel(const float* __restrict__ src,
                             __half* __restrict__ dst, int n4) {
  int i = blockIdx.x * blockDim.x + threadIdx.x;
  if (i >= n4) return;
  float4 f = ((const float4*)src)[i];
  __half2 a = __floats2half2_rn(f.x, f.y);
  __half2 b = __floats2half2_rn(f.z, f.w);
  uint2 u;
  u.x = *(const uint32_t*)&a;
  u.y = *(const uint32_t*)&b;
  ((uint2*)dst)[i] = u;
}

__global__ void convx_kernel(const float* __restrict__ src,
                             __half* __restrict__ dhi,
                             __half* __restrict__ dlo, int n4) {
  int i = blockIdx.x * blockDim.x + threadIdx.x;
  if (i >= n4) return;
  float4 f = ((const float4*)src)[i];
  __half2 a = __floats2half2_rn(f.x, f.y);
  __half2 b = __floats2half2_rn(f.z, f.w);
  __half2 al = __floats2half2_rn(f.x - __low2float(a), f.y - __high2float(a));
  __half2 bl = __floats2half2_rn(f.z - __low2float(b), f.w - __high2float(b));
  uint2 uh, ul;
  uh.x = *(const uint32_t*)&a;  uh.y = *(const uint32_t*)&b;
  ul.x = *(const uint32_t*)&al; ul.y = *(const uint32_t*)&bl;
  ((uint2*)dhi)[i] = uh;
  ((uint2*)dlo)[i] = ul;
}

// ---------------- router: logits -> top2 -> renorm ----------------
__global__ void router_kernel(const float* __restrict__ x,
                              const float* __restrict__ gw, int T) {
  int gwarp = (blockIdx.x * blockDim.x + threadIdx.x) >> 5;
  int lane = threadIdx.x & 31;
  if (gwarp >= T) return;
  const float* xr = x + (size_t)gwarp * HDIM;
  float acc[NEXP];
#pragma unroll
  for (int j = 0; j < NEXP; j++) acc[j] = 0.f;
  for (int k = lane; k < HDIM; k += 32) {
    float xv = xr[k];
    const float4* g4 = (const float4*)(gw + (size_t)k * NEXP);
#pragma unroll
    for (int q = 0; q < 4; q++) {
      float4 g = g4[q];
      acc[q * 4 + 0] += xv * g.x;
      acc[q * 4 + 1] += xv * g.y;
      acc[q * 4 + 2] += xv * g.z;
      acc[q * 4 + 3] += xv * g.w;
    }
  }
#pragma unroll
  for (int j = 0; j < NEXP; j++) {
#pragma unroll
    for (int o = 16; o > 0; o >>= 1)
      acc[j] += __shfl_xor_sync(0xffffffffu, acc[j], o);
  }
  if (lane == 0) {
    float b = -3.4e38f, s = -3.4e38f;
    int bi = 0, si = 0;
#pragma unroll
    for (int j = 0; j < NEXP; j++) {
      float v = acc[j];
      if (v > b) { s = b; si = bi; b = v; bi = j; }
      else if (v > s) { s = v; si = j; }
    }
    float w0 = 1.f / (1.f + expf(s - b));
    g_topk_i[gwarp * 2 + 0] = bi;
    g_topk_i[gwarp * 2 + 1] = si;
    g_topk_w[gwarp * 2 + 0] = w0;
    g_topk_w[gwarp * 2 + 1] = 1.f - w0;
  }
}

// ---------------- routing bookkeeping ----------------
__global__ void zero_cnt_kernel() {
  if (threadIdx.x < NEXP) g_counts[threadIdx.x] = 0;
}
__global__ void hist_kernel(int R) {
  int i = blockIdx.x * blockDim.x + threadIdx.x;
  if (i < R) atomicAdd(&g_counts[g_topk_i[i]], 1);
}
__global__ void scan_kernel() {
  int s = 0;
  for (int e = 0; e < NEXP; e++) {
    g_offs[e] = s;
    g_cursors[e] = s;
    s += g_counts[e];
  }
  g_offs[NEXP] = s;
}
__global__ void scatter_kernel(int R) {
  int i = blockIdx.x * blockDim.x + threadIdx.x;
  if (i >= R) return;
  int e = g_topk_i[i];
  int pos = atomicAdd(&g_cursors[e], 1);
  g_rows_t[pos] = i >> 1;
  g_rows_w[pos] = g_topk_w[i];
}

// ============================================================
// GEMM1: h = silu(Xe@w1) * (Xe@w3)   (2-pass fp16 split on A)
// BM=128, BN=64 (per matrix), BK=32, 256 thr, warps 4Mx2N, warp tile 32x32
// smem/stage (halves): A_hi 128*40=5120 | A_lo 5120 | B1 32*72=2304 | B3 2304
// ============================================================
__global__ __launch_bounds__(256, 2) void gemm1_kernel(
    const __half* __restrict__ w1, const __half* __restrict__ w3) {
  extern __shared__ __half sm[];
  const int e = blockIdx.z;
  const int base = g_offs[e];
  const int cnt = g_offs[e + 1] - base;
  const int m0 = blockIdx.x * 128;
  if (m0 >= cnt) return;
  const int n0 = blockIdx.y * 64;

  const int tid = threadIdx.x, lane = tid & 31, warp = tid >> 5;
  const int wm = warp >> 1, wn = warp & 1;

  // fill setup
  const int ar = tid >> 1, ak = (tid & 1) * 16;
  const int arow = m0 + ar;
  const int tokA = g_rows_t[base + (arow < cnt ? arow : 0)];
  const __half* pxh = g_xh + (size_t)tokA * HDIM + ak;
  const __half* pxl = g_xl + (size_t)tokA * HDIM + ak;
  const int bkr = tid >> 3, bc = (tid & 7) * 8;
  const size_t woff = (size_t)e * HDIM * IDIM + (size_t)bkr * IDIM + n0 + bc;
  const __half* pb1 = w1 + woff;
  const __half* pb3 = w3 + woff;

  const uint32_t sb = (uint32_t)__cvta_generic_to_shared(sm);
  const uint32_t dAh = sb + (uint32_t)(ar * 40 + ak) * 2;
  const uint32_t dAl = dAh + 5120 * 2;
  const uint32_t dB1 = sb + (uint32_t)(10240 + bkr * 72 + bc) * 2;
  const uint32_t dB3 = dB1 + 2304 * 2;
  constexpr uint32_t SST = 14848 * 2;  // bytes per stage

#define G1FILL(kt, s)                                                         \
  do {                                                                        \
    uint32_t so = (uint32_t)(s)*SST;                                          \
    const __half* a1 = pxh + (size_t)(kt) * 32;                               \
    const __half* a2 = pxl + (size_t)(kt) * 32;                               \
    CP16(dAh + so, a1);       CP16(dAh + so + 16, a1 + 8);                    \
    CP16(dAl + so, a2);       CP16(dAl + so + 16, a2 + 8);                    \
    const __half* b1 = pb1 + (size_t)(kt) * 32 * IDIM;                        \
    const __half* b3 = pb3 + (size_t)(kt) * 32 * IDIM;                        \
    CP16(dB1 + so, b1);       CP16(dB3 + so, b3);                             \
  } while (0)

  // mma addressing
  const int a_r = wm * 32 + (lane & 15);
  const int a_k = (lane >> 4) * 8;
  const uint32_t aA = sb + (uint32_t)(a_r * 40 + a_k) * 2;
  const int b_r = lane & 15;
  const int b_c = wn * 32 + (lane >> 4) * 8;
  const uint32_t aB = sb + (uint32_t)(10240 + b_r * 72 + b_c) * 2;

  float accg[2][4][4] = {}, accu[2][4][4] = {};
  const int KT = HDIM / 32;  // 64

  G1FILL(0, 0); CPCOMMIT();
  G1FILL(1, 1); CPCOMMIT();

  int s = 0;
  for (int kt = 0; kt < KT; kt++) {
    CPWAIT1();
    __syncthreads();
    if (kt + 2 < KT) {
      int s2 = s + 2; if (s2 >= 3) s2 -= 3;
      G1FILL(kt + 2, s2);
    }
    CPCOMMIT();
    const uint32_t so = (uint32_t)s * SST;
#pragma unroll
    for (int ks = 0; ks < 2; ks++) {
      uint32_t ahf[2][4], alf[2][4];
#pragma unroll
      for (int mt = 0; mt < 2; mt++) {
        uint32_t addr = aA + so + (uint32_t)(mt * 16 * 40 + ks * 16) * 2;
        LDSM4(ahf[mt], addr);
        LDSM4(alf[mt], addr + 5120 * 2);
      }
      uint32_t b1f[2][4], b3f[2][4];
#pragma unroll
      for (int h = 0; h < 2; h++) {
        uint32_t addr = aB + so + (uint32_t)(ks * 16 * 72 + h * 16) * 2;
        LDSM4T(b1f[h], addr);
        LDSM4T(b3f[h], addr + 2304 * 2);
      }
#pragma unroll
      for (int mt = 0; mt < 2; mt++) {
#pragma unroll
        for (int nt = 0; nt < 4; nt++) {
          const uint32_t* q1 = &b1f[nt >> 1][(nt & 1) * 2];
          const uint32_t* q3 = &b3f[nt >> 1][(nt & 1) * 2];
          MMAF16(accg[mt][nt], ahf[mt], q1);
          MMAF16(accg[mt][nt], alf[mt], q1);
          MMAF16(accu[mt][nt], ahf[mt], q3);
          MMAF16(accu[mt][nt], alf[mt], q3);
        }
      }
    }
    s = s + 1; if (s == 3) s = 0;
  }

  // epilogue: silu(g)*u -> hbuf (fp16 hi/lo)
#pragma unroll
  for (int mt = 0; mt < 2; mt++) {
    int rb = wm * 32 + mt * 16 + (lane >> 2);
#pragma unroll
    for (int hlf = 0; hlf < 2; hlf++) {
      int r = rb + hlf * 8;
      if (m0 + r >= cnt) continue;
      size_t rowb = (size_t)(base + m0 + r) * IDIM + n0 + wn * 32;
#pragma unroll
      for (int nt = 0; nt < 4; nt++) {
        float gg0 = accg[mt][nt][hlf * 2 + 0], gg1 = accg[mt][nt][hlf * 2 + 1];
        float uu0 = accu[mt][nt][hlf * 2 + 0], uu1 = accu[mt][nt][hlf * 2 + 1];
        float h0 = gg0 / (1.f + __expf(-gg0)) * uu0;
        float h1 = gg1 / (1.f + __expf(-gg1)) * uu1;
        __half h0h = __float2half_rn(h0), h1h = __float2half_rn(h1);
        __half2 hp = __halves2half2(h0h, h1h);
        __half2 lp = __floats2half2_rn(h0 - __half2float(h0h),
                                       h1 - __half2float(h1h));
        int col = nt * 8 + (lane & 3) * 2;
        *(__half2*)&g_hh[rowb + col] = hp;
        *(__half2*)&g_hl[rowb + col] = lp;
      }
    }
  }
}

// ============================================================
// GEMM2: out[t] += w * (h @ w2_e)    (2-pass fp16 split on A)
// BM=128, BN=128, BK=32, 256 thr, warps 4Mx2N, warp tile 32x64
// smem/stage (halves): A_hi 5120 | A_lo 5120 | B 32*136=4352
// ============================================================
__global__ __launch_bounds__(256, 2) void gemm2_kernel(
    const __half* __restrict__ w2, float* __restrict__ out) {
  extern __shared__ __half sm[];
  const int e = blockIdx.z;
  const int base = g_offs[e];
  const int cnt = g_offs[e + 1] - base;
  const int m0 = blockIdx.x * 128;
  if (m0 >= cnt) return;
  const int n0 = blockIdx.y * 128;

  const int tid = threadIdx.x, lane = tid & 31, warp = tid >> 5;
  const int wm = warp >> 1, wn = warp & 1;

  const int ar = tid >> 1, ak = (tid & 1) * 16;
  const int arow = m0 + ar;
  const int aidx = base + (arow < cnt ? arow : cnt - 1);
  const __half* pah = g_hh + (size_t)aidx * IDIM + ak;
  const __half* pal = g_hl + (size_t)aidx * IDIM + ak;
  const int bkr = tid >> 3, bc = (tid & 7) * 8;
  const __half* pb = w2 + (size_t)e * IDIM * HDIM + (size_t)bkr * HDIM + n0 + bc;

  const uint32_t sb = (uint32_t)__cvta_generic_to_shared(sm);
  const uint32_t dAh = sb + (uint32_t)(ar * 40 + ak) * 2;
  const uint32_t dAl = dAh + 5120 * 2;
  const uint32_t dB = sb + (uint32_t)(10240 + bkr * 136 + bc) * 2;
  constexpr uint32_t SST = 14592 * 2;

#define G2FILL(kt, s)                                                         \
  do {                                                                        \
    uint32_t so = (uint32_t)(s)*SST;                                          \
    const __half* a1 = pah + (size_t)(kt) * 32;                               \
    const __half* a2 = pal + (size_t)(kt) * 32;                               \
    CP16(dAh + so, a1);       CP16(dAh + so + 16, a1 + 8);                    \
    CP16(dAl + so, a2);       CP16(dAl + so + 16, a2 + 8);                    \
    const __half* b = pb + (size_t)(kt) * 32 * HDIM;                          \
    CP16(dB + so, b);         CP16(dB + so + 128, b + 64);                    \
  } while (0)

  const int a_r = wm * 32 + (lane & 15);
  const int a_k = (lane >> 4) * 8;
  const uint32_t aA = sb + (uint32_t)(a_r * 40 + a_k) * 2;
  const int b_r = lane & 15;
  const int b_c0 = wn * 64 + (lane >> 4) * 8;
  const uint32_t aB = sb + (uint32_t)(10240 + b_r * 136 + b_c0) * 2;

  float acc[2][8][4] = {};
  const int KT = IDIM / 32;  // 44

  G2FILL(0, 0); CPCOMMIT();
  G2FILL(1, 1); CPCOMMIT();

  int s = 0;
  for (int kt = 0; kt < KT; kt++) {
    CPWAIT1();
    __syncthreads();
    if (kt + 2 < KT) {
      int s2 = s + 2; if (s2 >= 3) s2 -= 3;
      G2FILL(kt + 2, s2);
    }
    CPCOMMIT();
    const uint32_t so = (uint32_t)s * SST;
#pragma unroll
    for (int ks = 0; ks < 2; ks++) {
      uint32_t ahf[2][4], alf[2][4];
#pragma unroll
      for (int mt = 0; mt < 2; mt++) {
        uint32_t addr = aA + so + (uint32_t)(mt * 16 * 40 + ks * 16) * 2;
        LDSM4(ahf[mt], addr);
        LDSM4(alf[mt], addr + 5120 * 2);
      }
      uint32_t bf[4][4];
#pragma unroll
      for (int h = 0; h < 4; h++) {
        uint32_t addr = aB + so + (uint32_t)(ks * 16 * 136 + h * 16) * 2;
        LDSM4T(bf[h], addr);
      }
#pragma unroll
      for (int mt = 0; mt < 2; mt++) {
#pragma unroll
        for (int nt = 0; nt < 8; nt++) {
          const uint32_t* q = &bf[nt >> 1][(nt & 1) * 2];
          MMAF16(acc[mt][nt], ahf[mt], q);
          MMAF16(acc[mt][nt], alf[mt], q);
        }
      }
    }
    s = s + 1; if (s == 3) s = 0;
  }

  // epilogue: weighted atomic scatter-add
#pragma unroll
  for (int mt = 0; mt < 2; mt++) {
    int rb = wm * 32 + mt * 16 + (lane >> 2);
#pragma unroll
    for (int hlf = 0; hlf < 2; hlf++) {
      int r = rb + hlf * 8;
      int gr = m0 + r;
      if (gr >= cnt) continue;
      int tok = g_rows_t[base + gr];
      float w = g_rows_w[base + gr];
      float* orow = out + (size_t)tok * HDIM + n0 + wn * 64;
#pragma unroll
      for (int nt = 0; nt < 8; nt++) {
        int col = nt * 8 + (lane & 3) * 2;
        atomicAdd(&orow[col], acc[mt][nt][hlf * 2 + 0] * w);
        atomicAdd(&orow[col + 1], acc[mt][nt][hlf * 2 + 1] * w);
      }
    }
  }
}

// ---------------- launch ----------------
extern "C" void kernel_launch(void* const* d_in, const int* in_sizes, int n_in,
                              void* d_out, int out_size) {
  const float* x  = (const float*)d_in[0];
  const float* gw = (const float*)d_in[1];
  const float* w1 = (const float*)d_in[2];
  const float* w3 = (const float*)d_in[3];
  const float* w2 = (const float*)d_in[4];
  float* out = (float*)d_out;

  const int T = in_sizes[0] / HDIM;  // 8192
  const int R = 2 * T;

  cudaMemsetAsync(out, 0, (size_t)out_size * sizeof(float), 0);

  // resolve device scratch addresses
  __half *w1h, *w3h, *w2h, *xh, *xl;
  cudaGetSymbolAddress((void**)&w1h, g_w1h);
  cudaGetSymbolAddress((void**)&w3h, g_w3h);
  cudaGetSymbolAddress((void**)&w2h, g_w2h);
  cudaGetSymbolAddress((void**)&xh, g_xh);
  cudaGetSymbolAddress((void**)&xl, g_xl);

  const int nw4 = NEXP * HDIM * IDIM / 4;
  convw_kernel<<<(nw4 + 255) / 256, 256>>>(w1, w1h, nw4);
  convw_kernel<<<(nw4 + 255) / 256, 256>>>(w3, w3h, nw4);
  convw_kernel<<<(nw4 + 255) / 256, 256>>>(w2, w2h, nw4);
  const int nx4 = T * HDIM / 4;
  convx_kernel<<<(nx4 + 255) / 256, 256>>>(x, xh, xl, nx4);

  zero_cnt_kernel<<<1, 32>>>();
  router_kernel<<<(T + 7) / 8, 256>>>(x, gw, T);
  hist_kernel<<<(R + 255) / 256, 256>>>(R);
  scan_kernel<<<1, 1>>>();
  scatter_kernel<<<(R + 255) / 256, 256>>>(R);

  cudaFuncSetAttribute(gemm1_kernel, cudaFuncAttributeMaxDynamicSharedMemorySize,
                       14848 * 2 * 3);
  cudaFuncSetAttribute(gemm2_kernel, cudaFuncAttributeMaxDynamicSharedMemorySize,
                       14592 * 2 * 3);

  const int mtiles = (T + 127) / 128;
  dim3 g1(mtiles, IDIM / 64, NEXP);
  gemm1_kernel<<<g1, 256, 14848 * 2 * 3>>>(w1h, w3h);
  dim3 g2(mtiles, HDIM / 128, NEXP);
  gemm2_kernel<<<g2, 256, 14592 * 2 * 3>>>(w2h, out);
}

// round 4
// speedup vs baseline: 2.4408x; 1.5939x over previous
#include <cuda_runtime.h>
#include <cuda_fp16.h>
#include <cstdint>

// ---------------- problem constants ----------------
constexpr int HDIM = 2048;
constexpr int IDIM = 1408;
constexpr int NEXP = 16;
constexpr int TMAX = 8192;
constexpr int RMAX = 2 * TMAX;

// ---------------- device scratch (static, no runtime allocs) ----------------
__device__ int   g_offs[NEXP + 1];
__device__ int   g_topk_i[RMAX];
__device__ float g_topk_w[RMAX];
__device__ int   g_rows_t[RMAX];
__device__ float g_rows_w[RMAX];

__device__ alignas(16) __half g_w1h[(size_t)NEXP * HDIM * IDIM];  // [e][K=H][N=I]
__device__ alignas(16) __half g_w3h[(size_t)NEXP * HDIM * IDIM];
__device__ alignas(16) __half g_w2h[(size_t)NEXP * IDIM * HDIM];  // [e][K=I][N=H]
__device__ alignas(16) __half g_xh[(size_t)TMAX * HDIM];
__device__ alignas(16) __half g_hh[(size_t)RMAX * IDIM];

// ---------------- asm helpers ----------------
#define LDSM4(R, addr)                                                        \
  asm volatile("ldmatrix.sync.aligned.m8n8.x4.shared.b16 {%0,%1,%2,%3},[%4];" \
               : "=r"((R)[0]), "=r"((R)[1]), "=r"((R)[2]), "=r"((R)[3])       \
               : "r"(addr))

#define LDSM4T(R, addr)                                                             \
  asm volatile("ldmatrix.sync.aligned.m8n8.x4.trans.shared.b16 {%0,%1,%2,%3},[%4];" \
               : "=r"((R)[0]), "=r"((R)[1]), "=r"((R)[2]), "=r"((R)[3])             \
               : "r"(addr))

#define MMAF16(D, A, B)                                                       \
  asm volatile("mma.sync.aligned.m16n8k16.row.col.f32.f16.f16.f32 "           \
               "{%0,%1,%2,%3},{%4,%5,%6,%7},{%8,%9},{%0,%1,%2,%3};"           \
               : "+f"((D)[0]), "+f"((D)[1]), "+f"((D)[2]), "+f"((D)[3])       \
               : "r"((A)[0]), "r"((A)[1]), "r"((A)[2]), "r"((A)[3]),          \
                 "r"((B)[0]), "r"((B)[1]))

#define CP16(dst, src)                                                        \
  asm volatile("cp.async.cg.shared.global [%0],[%1],16;" ::"r"(dst), "l"(src))
#define CPCOMMIT() asm volatile("cp.async.commit_group;")
#define CPWAIT1() asm volatile("cp.async.wait_group 1;")

// ---------------- conversion pre-passes ----------------
__global__ void convw_kernel(const float* __restrict__ src,
                             __half* __restrict__ dst, int n4) {
  int i = blockIdx.x * blockDim.x + threadIdx.x;
  if (i >= n4) return;
  float4 f = ((const float4*)src)[i];
  __half2 a = __floats2half2_rn(f.x, f.y);
  __half2 b = __floats2half2_rn(f.z, f.w);
  uint2 u;
  u.x = *(const uint32_t*)&a;
  u.y = *(const uint32_t*)&b;
  ((uint2*)dst)[i] = u;
}

// ---------------- router: logits -> top2 -> renorm ----------------
__global__ void router_kernel(const float* __restrict__ x,
                              const float* __restrict__ gw, int T) {
  int gwarp = (blockIdx.x * blockDim.x + threadIdx.x) >> 5;
  int lane = threadIdx.x & 31;
  if (gwarp >= T) return;
  const float* xr = x + (size_t)gwarp * HDIM;
  float acc[NEXP];
#pragma unroll
  for (int j = 0; j < NEXP; j++) acc[j] = 0.f;
  for (int k = lane; k < HDIM; k += 32) {
    float xv = xr[k];
    const float4* g4 = (const float4*)(gw + (size_t)k * NEXP);
#pragma unroll
    for (int q = 0; q < 4; q++) {
      float4 g = g4[q];
      acc[q * 4 + 0] += xv * g.x;
      acc[q * 4 + 1] += xv * g.y;
      acc[q * 4 + 2] += xv * g.z;
      acc[q * 4 + 3] += xv * g.w;
    }
  }
#pragma unroll
  for (int j = 0; j < NEXP; j++) {
#pragma unroll
    for (int o = 16; o > 0; o >>= 1)
      acc[j] += __shfl_xor_sync(0xffffffffu, acc[j], o);
  }
  if (lane == 0) {
    float b = -3.4e38f, s = -3.4e38f;
    int bi = 0, si = 0;
#pragma unroll
    for (int j = 0; j < NEXP; j++) {
      float v = acc[j];
      if (v > b) { s = b; si = bi; b = v; bi = j; }
      else if (v > s) { s = v; si = j; }
    }
    float w0 = 1.f / (1.f + expf(s - b));
    g_topk_i[gwarp * 2 + 0] = bi;
    g_topk_i[gwarp * 2 + 1] = si;
    g_topk_w[gwarp * 2 + 0] = w0;
    g_topk_w[gwarp * 2 + 1] = 1.f - w0;
  }
}

// ---------------- routing bookkeeping (single block) + x convert ----------
__global__ void route_build_kernel(int R) {
  __shared__ int cnt[NEXP], cur[NEXP];
  int tid = threadIdx.x;
  if (tid < NEXP) cnt[tid] = 0;
  __syncthreads();
  for (int i = tid; i < R; i += 256) atomicAdd(&cnt[g_topk_i[i]], 1);
  __syncthreads();
  if (tid == 0) {
    int s = 0;
    for (int e = 0; e < NEXP; e++) { g_offs[e] = s; cur[e] = s; s += cnt[e]; }
    g_offs[NEXP] = s;
  }
  __syncthreads();
  for (int i = tid; i < R; i += 256) {
    int e = g_topk_i[i];
    int p = atomicAdd(&cur[e], 1);
    g_rows_t[p] = i >> 1;
    g_rows_w[p] = g_topk_w[i];
  }
}

__global__ void convx_kernel(const float* __restrict__ src,
                             __half* __restrict__ dst, int n4) {
  int i = blockIdx.x * blockDim.x + threadIdx.x;
  if (i >= n4) return;
  float4 f = ((const float4*)src)[i];
  __half2 a = __floats2half2_rn(f.x, f.y);
  __half2 b = __floats2half2_rn(f.z, f.w);
  uint2 u;
  u.x = *(const uint32_t*)&a;
  u.y = *(const uint32_t*)&b;
  ((uint2*)dst)[i] = u;
}

// ============================================================
// GEMM1: h = silu(Xe@w1) * (Xe@w3)   (single-pass fp16)
// BM=128, BN=64 (per matrix), BK=32, 256 thr, warps 4Mx2N, warp tile 32x32
// smem/stage (halves): A 128*40=5120 | B1 32*72=2304 | B3 2304  = 9728
// ============================================================
constexpr uint32_t G1_SST = 9728u * 2;  // bytes per stage

__global__ __launch_bounds__(256, 2) void gemm1_kernel(
    const __half* __restrict__ w1, const __half* __restrict__ w3) {
  extern __shared__ __half sm[];
  const int e = blockIdx.z;
  const int base = g_offs[e];
  const int cnt = g_offs[e + 1] - base;
  const int m0 = blockIdx.x * 128;
  if (m0 >= cnt) return;
  const int n0 = blockIdx.y * 64;

  const int tid = threadIdx.x, lane = tid & 31, warp = tid >> 5;
  const int wm = warp >> 1, wn = warp & 1;

  // fill setup
  const int ar = tid >> 1, ak = (tid & 1) * 16;
  const int arow = m0 + ar;
  const int tokA = g_rows_t[base + (arow < cnt ? arow : 0)];
  const __half* pxh = g_xh + (size_t)tokA * HDIM + ak;
  const int bkr = tid >> 3, bc = (tid & 7) * 8;
  const size_t woff = (size_t)e * HDIM * IDIM + (size_t)bkr * IDIM + n0 + bc;
  const __half* pb1 = w1 + woff;
  const __half* pb3 = w3 + woff;

  const uint32_t sb = (uint32_t)__cvta_generic_to_shared(sm);
  const uint32_t dA = sb + (uint32_t)(ar * 40 + ak) * 2;
  const uint32_t dB1 = sb + (uint32_t)(5120 + bkr * 72 + bc) * 2;
  const uint32_t dB3 = dB1 + 2304 * 2;

#define G1FILL(kt, s)                                                         \
  do {                                                                        \
    uint32_t so = (uint32_t)(s)*G1_SST;                                       \
    const __half* a1 = pxh + (size_t)(kt) * 32;                               \
    CP16(dA + so, a1);                                                        \
    CP16(dA + so + 16, a1 + 8);                                               \
    const __half* b1 = pb1 + (size_t)(kt) * 32 * IDIM;                        \
    const __half* b3 = pb3 + (size_t)(kt) * 32 * IDIM;                        \
    CP16(dB1 + so, b1);                                                       \
    CP16(dB3 + so, b3);                                                       \
  } while (0)

  // mma addressing
  const int a_r = wm * 32 + (lane & 15);
  const int a_k = (lane >> 4) * 8;
  const uint32_t aA = sb + (uint32_t)(a_r * 40 + a_k) * 2;
  const int b_r = lane & 15;
  const int b_c = wn * 32 + (lane >> 4) * 8;
  const uint32_t aB = sb + (uint32_t)(5120 + b_r * 72 + b_c) * 2;

  float accg[2][4][4] = {}, accu[2][4][4] = {};
  const int KT = HDIM / 32;  // 64

  G1FILL(0, 0); CPCOMMIT();
  G1FILL(1, 1); CPCOMMIT();

  int s = 0;
  for (int kt = 0; kt < KT; kt++) {
    CPWAIT1();
    __syncthreads();
    if (kt + 2 < KT) {
      int s2 = s + 2; if (s2 >= 3) s2 -= 3;
      G1FILL(kt + 2, s2);
    }
    CPCOMMIT();
    const uint32_t so = (uint32_t)s * G1_SST;
#pragma unroll
    for (int ks = 0; ks < 2; ks++) {
      uint32_t af[2][4];
#pragma unroll
      for (int mt = 0; mt < 2; mt++) {
        uint32_t addr = aA + so + (uint32_t)(mt * 16 * 40 + ks * 16) * 2;
        LDSM4(af[mt], addr);
      }
      uint32_t b1f[2][4], b3f[2][4];
#pragma unroll
      for (int h = 0; h < 2; h++) {
        uint32_t addr = aB + so + (uint32_t)(ks * 16 * 72 + h * 16) * 2;
        LDSM4T(b1f[h], addr);
        LDSM4T(b3f[h], addr + 2304 * 2);
      }
#pragma unroll
      for (int mt = 0; mt < 2; mt++) {
#pragma unroll
        for (int nt = 0; nt < 4; nt++) {
          const uint32_t* q1 = &b1f[nt >> 1][(nt & 1) * 2];
          const uint32_t* q3 = &b3f[nt >> 1][(nt & 1) * 2];
          MMAF16(accg[mt][nt], af[mt], q1);
          MMAF16(accu[mt][nt], af[mt], q3);
        }
      }
    }
    s = s + 1; if (s == 3) s = 0;
  }

  // epilogue: silu(g)*u -> g_hh (fp16)
#pragma unroll
  for (int mt = 0; mt < 2; mt++) {
    int rb = wm * 32 + mt * 16 + (lane >> 2);
#pragma unroll
    for (int hlf = 0; hlf < 2; hlf++) {
      int r = rb + hlf * 8;
      if (m0 + r >= cnt) continue;
      size_t rowb = (size_t)(base + m0 + r) * IDIM + n0 + wn * 32;
#pragma unroll
      for (int nt = 0; nt < 4; nt++) {
        float gg0 = accg[mt][nt][hlf * 2 + 0], gg1 = accg[mt][nt][hlf * 2 + 1];
        float uu0 = accu[mt][nt][hlf * 2 + 0], uu1 = accu[mt][nt][hlf * 2 + 1];
        float h0 = gg0 / (1.f + __expf(-gg0)) * uu0;
        float h1 = gg1 / (1.f + __expf(-gg1)) * uu1;
        int col = nt * 8 + (lane & 3) * 2;
        *(__half2*)&g_hh[rowb + col] = __floats2half2_rn(h0, h1);
      }
    }
  }
}

// ============================================================
// GEMM2: out[t] += w * (h @ w2_e)    (single-pass fp16)
// BM=128, BN=128, BK=32, 256 thr, warps 4Mx2N, warp tile 32x64
// smem/stage (halves): A 5120 | B 32*136=4352  = 9472
// ============================================================
constexpr uint32_t G2_SST = 9472u * 2;

__global__ __launch_bounds__(256, 2) void gemm2_kernel(
    const __half* __restrict__ w2, float* __restrict__ out) {
  extern __shared__ __half sm[];
  const int e = blockIdx.z;
  const int base = g_offs[e];
  const int cnt = g_offs[e + 1] - base;
  const int m0 = blockIdx.x * 128;
  if (m0 >= cnt) return;
  const int n0 = blockIdx.y * 128;

  const int tid = threadIdx.x, lane = tid & 31, warp = tid >> 5;
  const int wm = warp >> 1, wn = warp & 1;

  const int ar = tid >> 1, ak = (tid & 1) * 16;
  const int arow = m0 + ar;
  const int aidx = base + (arow < cnt ? arow : cnt - 1);
  const __half* pah = g_hh + (size_t)aidx * IDIM + ak;
  const int bkr = tid >> 3, bc = (tid & 7) * 8;
  const __half* pb = w2 + (size_t)e * IDIM * HDIM + (size_t)bkr * HDIM + n0 + bc;

  const uint32_t sb = (uint32_t)__cvta_generic_to_shared(sm);
  const uint32_t dA = sb + (uint32_t)(ar * 40 + ak) * 2;
  const uint32_t dB = sb + (uint32_t)(5120 + bkr * 136 + bc) * 2;

#define G2FILL(kt, s)                                                         \
  do {                                                                        \
    uint32_t so = (uint32_t)(s)*G2_SST;                                       \
    const __half* a1 = pah + (size_t)(kt) * 32;                               \
    CP16(dA + so, a1);                                                        \
    CP16(dA + so + 16, a1 + 8);                                               \
    const __half* b = pb + (size_t)(kt) * 32 * HDIM;                          \
    CP16(dB + so, b);                                                         \
    CP16(dB + so + 128, b + 64);                                              \
  } while (0)

  const int a_r = wm * 32 + (lane & 15);
  const int a_k = (lane >> 4) * 8;
  const uint32_t aA = sb + (uint32_t)(a_r * 40 + a_k) * 2;
  const int b_r = lane & 15;
  const int b_c0 = wn * 64 + (lane >> 4) * 8;
  const uint32_t aB = sb + (uint32_t)(5120 + b_r * 136 + b_c0) * 2;

  float acc[2][8][4] = {};
  const int KT = IDIM / 32;  // 44

  G2FILL(0, 0); CPCOMMIT();
  G2FILL(1, 1); CPCOMMIT();

  int s = 0;
  for (int kt = 0; kt < KT; kt++) {
    CPWAIT1();
    __syncthreads();
    if (kt + 2 < KT) {
      int s2 = s + 2; if (s2 >= 3) s2 -= 3;
      G2FILL(kt + 2, s2);
    }
    CPCOMMIT();
    const uint32_t so = (uint32_t)s * G2_SST;
#pragma unroll
    for (int ks = 0; ks < 2; ks++) {
      uint32_t af[2][4];
#pragma unroll
      for (int mt = 0; mt < 2; mt++) {
        uint32_t addr = aA + so + (uint32_t)(mt * 16 * 40 + ks * 16) * 2;
        LDSM4(af[mt], addr);
      }
      uint32_t bf[4][4];
#pragma unroll
      for (int h = 0; h < 4; h++) {
        uint32_t addr = aB + so + (uint32_t)(ks * 16 * 136 + h * 16) * 2;
        LDSM4T(bf[h], addr);
      }
#pragma unroll
      for (int mt = 0; mt < 2; mt++) {
#pragma unroll
        for (int nt = 0; nt < 8; nt++) {
          const uint32_t* q = &bf[nt >> 1][(nt & 1) * 2];
          MMAF16(acc[mt][nt], af[mt], q);
        }
      }
    }
    s = s + 1; if (s == 3) s = 0;
  }

  // epilogue: weighted atomic scatter-add
#pragma unroll
  for (int mt = 0; mt < 2; mt++) {
    int rb = wm * 32 + mt * 16 + (lane >> 2);
#pragma unroll
    for (int hlf = 0; hlf < 2; hlf++) {
      int r = rb + hlf * 8;
      int gr = m0 + r;
      if (gr >= cnt) continue;
      int tok = g_rows_t[base + gr];
      float w = g_rows_w[base + gr];
      float* orow = out + (size_t)tok * HDIM + n0 + wn * 64;
#pragma unroll
      for (int nt = 0; nt < 8; nt++) {
        int col = nt * 8 + (lane & 3) * 2;
        atomicAdd(&orow[col], acc[mt][nt][hlf * 2 + 0] * w);
        atomicAdd(&orow[col + 1], acc[mt][nt][hlf * 2 + 1] * w);
      }
    }
  }
}

// ---------------- launch ----------------
extern "C" void kernel_launch(void* const* d_in, const int* in_sizes, int n_in,
                              void* d_out, int out_size) {
  const float* x  = (const float*)d_in[0];
  const float* gw = (const float*)d_in[1];
  const float* w1 = (const float*)d_in[2];
  const float* w3 = (const float*)d_in[3];
  const float* w2 = (const float*)d_in[4];
  float* out = (float*)d_out;

  const int T = in_sizes[0] / HDIM;  // 8192
  const int R = 2 * T;

  cudaMemsetAsync(out, 0, (size_t)out_size * sizeof(float), 0);

  __half *w1h, *w3h, *w2h, *xh;
  cudaGetSymbolAddress((void**)&w1h, g_w1h);
  cudaGetSymbolAddress((void**)&w3h, g_w3h);
  cudaGetSymbolAddress((void**)&w2h, g_w2h);
  cudaGetSymbolAddress((void**)&xh, g_xh);

  cudaFuncSetAttribute(gemm1_kernel, cudaFuncAttributeMaxDynamicSharedMemorySize,
                       (int)(G1_SST * 3));
  cudaFuncSetAttribute(gemm2_kernel, cudaFuncAttributeMaxDynamicSharedMemorySize,
                       (int)(G2_SST * 3));

  const int nw4 = NEXP * HDIM * IDIM / 4;
  // launch order arranged so ncu (-s 5 -c 1) profiles gemm1_kernel
  convw_kernel<<<(nw4 + 255) / 256, 256>>>(w1, w1h, nw4);             // 0
  convw_kernel<<<(nw4 + 255) / 256, 256>>>(w3, w3h, nw4);             // 1
  convx_kernel<<<(T * HDIM / 4 + 255) / 256, 256>>>(x, xh, T * HDIM / 4); // 2
  router_kernel<<<(T + 7) / 8, 256>>>(x, gw, T);                      // 3
  route_build_kernel<<<1, 256>>>(R);                                  // 4

  const int mtiles = (T + 127) / 128;  // 64
  dim3 g1(mtiles, IDIM / 64, NEXP);
  gemm1_kernel<<<g1, 256, G1_SST * 3>>>(w1h, w3h);                    // 5 <- profiled
  convw_kernel<<<(nw4 + 255) / 256, 256>>>(w2, w2h, nw4);             // 6
  dim3 g2(mtiles, HDIM / 128, NEXP);
  gemm2_kernel<<<g2, 256, G2_SST * 3>>>(w2h, out);                    // 7
}

// round 5
// speedup vs baseline: 2.6073x; 1.0682x over previous
#include <cuda_runtime.h>
#include <cuda_fp16.h>
#include <cstdint>

// ---------------- problem constants ----------------
constexpr int HDIM = 2048;
constexpr int IDIM = 1408;
constexpr int NEXP = 16;
constexpr int TMAX = 8192;
constexpr int RMAX = 2 * TMAX;

// ---------------- device scratch (static, no runtime allocs) ----------------
__device__ int   g_offs[NEXP + 1];
__device__ int   g_topk_i[RMAX];
__device__ float g_topk_w[RMAX];
__device__ int   g_rows_t[RMAX];
__device__ float g_rows_w[RMAX];

__device__ alignas(16) __half g_w1h[(size_t)NEXP * HDIM * IDIM];  // [e][K=H][N=I]
__device__ alignas(16) __half g_w3h[(size_t)NEXP * HDIM * IDIM];
__device__ alignas(16) __half g_w2h[(size_t)NEXP * IDIM * HDIM];  // [e][K=I][N=H]
__device__ alignas(16) __half g_xh[(size_t)TMAX * HDIM];
__device__ alignas(16) __half g_hh[(size_t)RMAX * IDIM];

// ---------------- asm helpers ----------------
#define LDSM4(R, addr)                                                        \
  asm volatile("ldmatrix.sync.aligned.m8n8.x4.shared.b16 {%0,%1,%2,%3},[%4];" \
               : "=r"((R)[0]), "=r"((R)[1]), "=r"((R)[2]), "=r"((R)[3])       \
               : "r"(addr))

#define LDSM4T(R, addr)                                                             \
  asm volatile("ldmatrix.sync.aligned.m8n8.x4.trans.shared.b16 {%0,%1,%2,%3},[%4];" \
               : "=r"((R)[0]), "=r"((R)[1]), "=r"((R)[2]), "=r"((R)[3])             \
               : "r"(addr))

#define MMAF16(D, A, B)                                                       \
  asm volatile("mma.sync.aligned.m16n8k16.row.col.f32.f16.f16.f32 "           \
               "{%0,%1,%2,%3},{%4,%5,%6,%7},{%8,%9},{%0,%1,%2,%3};"           \
               : "+f"((D)[0]), "+f"((D)[1]), "+f"((D)[2]), "+f"((D)[3])       \
               : "r"((A)[0]), "r"((A)[1]), "r"((A)[2]), "r"((A)[3]),          \
                 "r"((B)[0]), "r"((B)[1]))

#define CP16(dst, src)                                                        \
  asm volatile("cp.async.cg.shared.global [%0],[%1],16;" ::"r"(dst), "l"(src))
#define CPCOMMIT() asm volatile("cp.async.commit_group;")
#define CPWAIT1() asm volatile("cp.async.wait_group 1;")

// ---------------- fused conversion pre-pass (w1|w3|w2|x) ----------------
constexpr int NW4 = NEXP * HDIM * IDIM / 4;  // 11,534,336 float4 per weight
constexpr int NX4 = TMAX * HDIM / 4;         // 4,194,304 float4

__global__ void conv_all_kernel(const float* __restrict__ w1,
                                const float* __restrict__ w3,
                                const float* __restrict__ w2,
                                const float* __restrict__ x) {
  int i = blockIdx.x * blockDim.x + threadIdx.x;
  const float* src;
  __half* dst;
  int li;
  if (i < NW4) {
    src = w1; dst = g_w1h; li = i;
  } else if (i < 2 * NW4) {
    src = w3; dst = g_w3h; li = i - NW4;
  } else if (i < 3 * NW4) {
    src = w2; dst = g_w2h; li = i - 2 * NW4;
  } else {
    li = i - 3 * NW4;
    if (li >= NX4) return;
    src = x; dst = g_xh;
  }
  float4 f = ((const float4*)src)[li];
  __half2 a = __floats2half2_rn(f.x, f.y);
  __half2 b = __floats2half2_rn(f.z, f.w);
  uint2 u;
  u.x = *(const uint32_t*)&a;
  u.y = *(const uint32_t*)&b;
  ((uint2*)dst)[li] = u;
}

// ---------------- router v2: 4 tokens per warp ----------------
__global__ void router_kernel(const float* __restrict__ x,
                              const float* __restrict__ gw, int T) {
  const int gwarp = (blockIdx.x * blockDim.x + threadIdx.x) >> 5;
  const int lane = threadIdx.x & 31;
  const int t0 = gwarp * 4;
  if (t0 >= T) return;

  const float* xr0 = x + (size_t)t0 * HDIM;
  float acc[4][NEXP];
#pragma unroll
  for (int i = 0; i < 4; i++)
#pragma unroll
    for (int j = 0; j < NEXP; j++) acc[i][j] = 0.f;

  for (int k = lane; k < HDIM; k += 32) {
    const float4* g4 = (const float4*)(gw + (size_t)k * NEXP);
    float4 g0 = g4[0], g1 = g4[1], g2 = g4[2], g3 = g4[3];
    float xv0 = xr0[k];
    float xv1 = xr0[HDIM + k];
    float xv2 = xr0[2 * HDIM + k];
    float xv3 = xr0[3 * HDIM + k];
#define RSTEP(i, xv)                                                          \
    acc[i][0] += (xv)*g0.x;  acc[i][1] += (xv)*g0.y;                          \
    acc[i][2] += (xv)*g0.z;  acc[i][3] += (xv)*g0.w;                          \
    acc[i][4] += (xv)*g1.x;  acc[i][5] += (xv)*g1.y;                          \
    acc[i][6] += (xv)*g1.z;  acc[i][7] += (xv)*g1.w;                          \
    acc[i][8] += (xv)*g2.x;  acc[i][9] += (xv)*g2.y;                          \
    acc[i][10] += (xv)*g2.z; acc[i][11] += (xv)*g2.w;                         \
    acc[i][12] += (xv)*g3.x; acc[i][13] += (xv)*g3.y;                         \
    acc[i][14] += (xv)*g3.z; acc[i][15] += (xv)*g3.w;
    RSTEP(0, xv0) RSTEP(1, xv1) RSTEP(2, xv2) RSTEP(3, xv3)
#undef RSTEP
  }
  // full butterfly reduce: every lane ends with all 64 sums
#pragma unroll
  for (int i = 0; i < 4; i++)
#pragma unroll
    for (int j = 0; j < NEXP; j++) {
#pragma unroll
      for (int o = 16; o > 0; o >>= 1)
        acc[i][j] += __shfl_xor_sync(0xffffffffu, acc[i][j], o);
    }

  if (lane < 4) {
    float v[NEXP];
#pragma unroll
    for (int j = 0; j < NEXP; j++) {
      float t = acc[0][j];
      if (lane == 1) t = acc[1][j];
      if (lane == 2) t = acc[2][j];
      if (lane == 3) t = acc[3][j];
      v[j] = t;
    }
    float b = -3.4e38f, s = -3.4e38f;
    int bi = 0, si = 0;
#pragma unroll
    for (int j = 0; j < NEXP; j++) {
      float w = v[j];
      if (w > b) { s = b; si = bi; b = w; bi = j; }
      else if (w > s) { s = w; si = j; }
    }
    float w0 = 1.f / (1.f + expf(s - b));
    int t = t0 + lane;
    g_topk_i[t * 2 + 0] = bi;
    g_topk_i[t * 2 + 1] = si;
    g_topk_w[t * 2 + 0] = w0;
    g_topk_w[t * 2 + 1] = 1.f - w0;
  }
}

// ---------------- routing bookkeeping (single block) ----------------
__global__ void route_build_kernel(int R) {
  __shared__ int cnt[NEXP], cur[NEXP];
  int tid = threadIdx.x;
  if (tid < NEXP) cnt[tid] = 0;
  __syncthreads();
  for (int i = tid; i < R; i += 256) atomicAdd(&cnt[g_topk_i[i]], 1);
  __syncthreads();
  if (tid == 0) {
    int s = 0;
    for (int e = 0; e < NEXP; e++) { g_offs[e] = s; cur[e] = s; s += cnt[e]; }
    g_offs[NEXP] = s;
  }
  __syncthreads();
  for (int i = tid; i < R; i += 256) {
    int e = g_topk_i[i];
    int p = atomicAdd(&cur[e], 1);
    g_rows_t[p] = i >> 1;
    g_rows_w[p] = g_topk_w[i];
  }
}

// ============================================================
// GEMM1: h = silu(Xe@w1) * (Xe@w3)   (single-pass fp16)
// BM=128, BN=64 (per matrix), BK=32, 256 thr, warps 4Mx2N, warp tile 32x32
// smem/stage (halves): A 128*40=5120 | B1 32*72=2304 | B3 2304  = 9728
// ============================================================
constexpr uint32_t G1_SST = 9728u * 2;  // bytes per stage

__global__ __launch_bounds__(256, 2) void gemm1_kernel(
    const __half* __restrict__ w1, const __half* __restrict__ w3) {
  extern __shared__ __half sm[];
  const int e = blockIdx.z;
  const int base = g_offs[e];
  const int cnt = g_offs[e + 1] - base;
  const int m0 = blockIdx.x * 128;
  if (m0 >= cnt) return;
  const int n0 = blockIdx.y * 64;

  const int tid = threadIdx.x, lane = tid & 31, warp = tid >> 5;
  const int wm = warp >> 1, wn = warp & 1;

  const int ar = tid >> 1, ak = (tid & 1) * 16;
  const int arow = m0 + ar;
  const int tokA = g_rows_t[base + (arow < cnt ? arow : 0)];
  const __half* pxh = g_xh + (size_t)tokA * HDIM + ak;
  const int bkr = tid >> 3, bc = (tid & 7) * 8;
  const size_t woff = (size_t)e * HDIM * IDIM + (size_t)bkr * IDIM + n0 + bc;
  const __half* pb1 = w1 + woff;
  const __half* pb3 = w3 + woff;

  const uint32_t sb = (uint32_t)__cvta_generic_to_shared(sm);
  const uint32_t dA = sb + (uint32_t)(ar * 40 + ak) * 2;
  const uint32_t dB1 = sb + (uint32_t)(5120 + bkr * 72 + bc) * 2;
  const uint32_t dB3 = dB1 + 2304 * 2;

#define G1FILL(kt, s)                                                         \
  do {                                                                        \
    uint32_t so = (uint32_t)(s)*G1_SST;                                       \
    const __half* a1 = pxh + (size_t)(kt) * 32;                               \
    CP16(dA + so, a1);                                                        \
    CP16(dA + so + 16, a1 + 8);                                               \
    const __half* b1 = pb1 + (size_t)(kt) * 32 * IDIM;                        \
    const __half* b3 = pb3 + (size_t)(kt) * 32 * IDIM;                        \
    CP16(dB1 + so, b1);                                                       \
    CP16(dB3 + so, b3);                                                       \
  } while (0)

  const int a_r = wm * 32 + (lane & 15);
  const int a_k = (lane >> 4) * 8;
  const uint32_t aA = sb + (uint32_t)(a_r * 40 + a_k) * 2;
  const int b_r = lane & 15;
  const int b_c = wn * 32 + (lane >> 4) * 8;
  const uint32_t aB = sb + (uint32_t)(5120 + b_r * 72 + b_c) * 2;

  float accg[2][4][4] = {}, accu[2][4][4] = {};
  const int KT = HDIM / 32;  // 64

  G1FILL(0, 0); CPCOMMIT();
  G1FILL(1, 1); CPCOMMIT();

  int s = 0;
  for (int kt = 0; kt < KT; kt++) {
    CPWAIT1();
    __syncthreads();
    if (kt + 2 < KT) {
      int s2 = s + 2; if (s2 >= 3) s2 -= 3;
      G1FILL(kt + 2, s2);
    }
    CPCOMMIT();
    const uint32_t so = (uint32_t)s * G1_SST;
#pragma unroll
    for (int ks = 0; ks < 2; ks++) {
      uint32_t af[2][4];
#pragma unroll
      for (int mt = 0; mt < 2; mt++) {
        uint32_t addr = aA + so + (uint32_t)(mt * 16 * 40 + ks * 16) * 2;
        LDSM4(af[mt], addr);
      }
      uint32_t b1f[2][4], b3f[2][4];
#pragma unroll
      for (int h = 0; h < 2; h++) {
        uint32_t addr = aB + so + (uint32_t)(ks * 16 * 72 + h * 16) * 2;
        LDSM4T(b1f[h], addr);
        LDSM4T(b3f[h], addr + 2304 * 2);
      }
#pragma unroll
      for (int mt = 0; mt < 2; mt++) {
#pragma unroll
        for (int nt = 0; nt < 4; nt++) {
          const uint32_t* q1 = &b1f[nt >> 1][(nt & 1) * 2];
          const uint32_t* q3 = &b3f[nt >> 1][(nt & 1) * 2];
          MMAF16(accg[mt][nt], af[mt], q1);
          MMAF16(accu[mt][nt], af[mt], q3);
        }
      }
    }
    s = s + 1; if (s == 3) s = 0;
  }

  // epilogue: silu(g)*u -> g_hh (fp16)
#pragma unroll
  for (int mt = 0; mt < 2; mt++) {
    int rb = wm * 32 + mt * 16 + (lane >> 2);
#pragma unroll
    for (int hlf = 0; hlf < 2; hlf++) {
      int r = rb + hlf * 8;
      if (m0 + r >= cnt) continue;
      size_t rowb = (size_t)(base + m0 + r) * IDIM + n0 + wn * 32;
#pragma unroll
      for (int nt = 0; nt < 4; nt++) {
        float gg0 = accg[mt][nt][hlf * 2 + 0], gg1 = accg[mt][nt][hlf * 2 + 1];
        float uu0 = accu[mt][nt][hlf * 2 + 0], uu1 = accu[mt][nt][hlf * 2 + 1];
        float h0 = gg0 / (1.f + __expf(-gg0)) * uu0;
        float h1 = gg1 / (1.f + __expf(-gg1)) * uu1;
        int col = nt * 8 + (lane & 3) * 2;
        *(__half2*)&g_hh[rowb + col] = __floats2half2_rn(h0, h1);
      }
    }
  }
}

// ============================================================
// GEMM2: out[t] += w * (h @ w2_e)    (single-pass fp16)
// BM=128, BN=128, BK=32, 256 thr, warps 4Mx2N, warp tile 32x64
// smem/stage (halves): A 5120 | B 32*136=4352  = 9472
// ============================================================
constexpr uint32_t G2_SST = 9472u * 2;

__global__ __launch_bounds__(256, 2) void gemm2_kernel(
    const __half* __restrict__ w2, float* __restrict__ out) {
  extern __shared__ __half sm[];
  const int e = blockIdx.z;
  const int base = g_offs[e];
  const int cnt = g_offs[e + 1] - base;
  const int m0 = blockIdx.x * 128;
  if (m0 >= cnt) return;
  const int n0 = blockIdx.y * 128;

  const int tid = threadIdx.x, lane = tid & 31, warp = tid >> 5;
  const int wm = warp >> 1, wn = warp & 1;

  const int ar = tid >> 1, ak = (tid & 1) * 16;
  const int arow = m0 + ar;
  const int aidx = base + (arow < cnt ? arow : cnt - 1);
  const __half* pah = g_hh + (size_t)aidx * IDIM + ak;
  const int bkr = tid >> 3, bc = (tid & 7) * 8;
  const __half* pb = w2 + (size_t)e * IDIM * HDIM + (size_t)bkr * HDIM + n0 + bc;

  const uint32_t sb = (uint32_t)__cvta_generic_to_shared(sm);
  const uint32_t dA = sb + (uint32_t)(ar * 40 + ak) * 2;
  const uint32_t dB = sb + (uint32_t)(5120 + bkr * 136 + bc) * 2;

#define G2FILL(kt, s)                                                         \
  do {                                                                        \
    uint32_t so = (uint32_t)(s)*G2_SST;                                       \
    const __half* a1 = pah + (size_t)(kt) * 32;                               \
    CP16(dA + so, a1);                                                        \
    CP16(dA + so + 16, a1 + 8);                                               \
    const __half* b = pb + (size_t)(kt) * 32 * HDIM;                          \
    CP16(dB + so, b);                                                         \
    CP16(dB + so + 128, b + 64);                                              \
  } while (0)

  const int a_r = wm * 32 + (lane & 15);
  const int a_k = (lane >> 4) * 8;
  const uint32_t aA = sb + (uint32_t)(a_r * 40 + a_k) * 2;
  const int b_r = lane & 15;
  const int b_c0 = wn * 64 + (lane >> 4) * 8;
  const uint32_t aB = sb + (uint32_t)(5120 + b_r * 136 + b_c0) * 2;

  float acc[2][8][4] = {};
  const int KT = IDIM / 32;  // 44

  G2FILL(0, 0); CPCOMMIT();
  G2FILL(1, 1); CPCOMMIT();

  int s = 0;
  for (int kt = 0; kt < KT; kt++) {
    CPWAIT1();
    __syncthreads();
    if (kt + 2 < KT) {
      int s2 = s + 2; if (s2 >= 3) s2 -= 3;
      G2FILL(kt + 2, s2);
    }
    CPCOMMIT();
    const uint32_t so = (uint32_t)s * G2_SST;
#pragma unroll
    for (int ks = 0; ks < 2; ks++) {
      uint32_t af[2][4];
#pragma unroll
      for (int mt = 0; mt < 2; mt++) {
        uint32_t addr = aA + so + (uint32_t)(mt * 16 * 40 + ks * 16) * 2;
        LDSM4(af[mt], addr);
      }
      uint32_t bf[4][4];
#pragma unroll
      for (int h = 0; h < 4; h++) {
        uint32_t addr = aB + so + (uint32_t)(ks * 16 * 136 + h * 16) * 2;
        LDSM4T(bf[h], addr);
      }
#pragma unroll
      for (int mt = 0; mt < 2; mt++) {
#pragma unroll
        for (int nt = 0; nt < 8; nt++) {
          const uint32_t* q = &bf[nt >> 1][(nt & 1) * 2];
          MMAF16(acc[mt][nt], af[mt], q);
        }
      }
    }
    s = s + 1; if (s == 3) s = 0;
  }

  // epilogue: weighted atomic scatter-add
#pragma unroll
  for (int mt = 0; mt < 2; mt++) {
    int rb = wm * 32 + mt * 16 + (lane >> 2);
#pragma unroll
    for (int hlf = 0; hlf < 2; hlf++) {
      int r = rb + hlf * 8;
      int gr = m0 + r;
      if (gr >= cnt) continue;
      int tok = g_rows_t[base + gr];
      float w = g_rows_w[base + gr];
      float* orow = out + (size_t)tok * HDIM + n0 + wn * 64;
#pragma unroll
      for (int nt = 0; nt < 8; nt++) {
        int col = nt * 8 + (lane & 3) * 2;
        atomicAdd(&orow[col], acc[mt][nt][hlf * 2 + 0] * w);
        atomicAdd(&orow[col + 1], acc[mt][nt][hlf * 2 + 1] * w);
      }
    }
  }
}

// ---------------- launch ----------------
extern "C" void kernel_launch(void* const* d_in, const int* in_sizes, int n_in,
                              void* d_out, int out_size) {
  const float* x  = (const float*)d_in[0];
  const float* gw = (const float*)d_in[1];
  const float* w1 = (const float*)d_in[2];
  const float* w3 = (const float*)d_in[3];
  const float* w2 = (const float*)d_in[4];
  float* out = (float*)d_out;

  const int T = in_sizes[0] / HDIM;  // 8192
  const int R = 2 * T;

  cudaMemsetAsync(out, 0, (size_t)out_size * sizeof(float), 0);

  __half *w1h, *w3h, *w2h;
  cudaGetSymbolAddress((void**)&w1h, g_w1h);
  cudaGetSymbolAddress((void**)&w3h, g_w3h);
  cudaGetSymbolAddress((void**)&w2h, g_w2h);

  cudaFuncSetAttribute(gemm1_kernel, cudaFuncAttributeMaxDynamicSharedMemorySize,
                       (int)(G1_SST * 3));
  cudaFuncSetAttribute(gemm2_kernel, cudaFuncAttributeMaxDynamicSharedMemorySize,
                       (int)(G2_SST * 3));

  // launch order arranged so ncu profiles gemm1_kernel (4th kernel launch)
  const int ntot = 3 * NW4 + NX4;
  conv_all_kernel<<<(ntot + 255) / 256, 256>>>(w1, w3, w2, x);        // 1
  router_kernel<<<(T / 4 + 7) / 8, 256>>>(x, gw, T);                  // 2
  route_build_kernel<<<1, 256>>>(R);                                  // 3

  const int mtiles = (T + 127) / 128;  // 64
  dim3 g1(mtiles, IDIM / 64, NEXP);
  gemm1_kernel<<<g1, 256, G1_SST * 3>>>(w1h, w3h);                    // 4 <- profiled
  dim3 g2(mtiles, HDIM / 128, NEXP);
  gemm2_kernel<<<g2, 256, G2_SST * 3>>>(w2h, out);                    // 5
}